// round 15
// baseline (speedup 1.0000x reference)
#include <cuda_runtime.h>
#include <math.h>

#define HW   16384
#define CCH  192
#define BB   4
#define NH   8
#define HD   24
#define BH   (BB*NH)      // 32

// scratch (no allocations allowed)
__device__ float g_accum[BH * 624];     // per bh: 576 gram dots + 24 ssq_q + 24 ssq_k
__device__ float g_C[BB * CCH * CCH];   // combined (proj @ blockdiag(W)) per batch

// ---------------- packed fp32x2 helpers ----------------
__device__ __forceinline__ void ffma2(unsigned long long &d, unsigned long long a, unsigned long long b){
    asm("fma.rn.f32x2 %0, %1, %2, %0;" : "+l"(d) : "l"(a), "l"(b));
}
__device__ __forceinline__ unsigned long long dup2(float a){
    unsigned long long r; asm("mov.b64 %0, {%1, %1};" : "=l"(r) : "f"(a)); return r;
}
__device__ __forceinline__ float hsum2(unsigned long long v){
    float lo, hi; asm("mov.b64 {%0, %1}, %2;" : "=f"(lo), "=f"(hi) : "l"(v)); return lo + hi;
}
__device__ __forceinline__ float2 unpack2(unsigned long long v){
    float2 r; asm("mov.b64 {%0, %1}, %2;" : "=f"(r.x), "=f"(r.y) : "l"(v)); return r;
}

// ---------------- cp.async helpers ----------------
__device__ __forceinline__ void cp_async16(unsigned int saddr, const void* gptr){
    asm volatile("cp.async.cg.shared.global [%0], [%1], 16;" :: "r"(saddr), "l"(gptr) : "memory");
}
__device__ __forceinline__ void cp_commit(){ asm volatile("cp.async.commit_group;" ::: "memory"); }
template<int N>
__device__ __forceinline__ void cp_wait(){ asm volatile("cp.async.wait_group %0;" :: "n"(N) : "memory"); }

// ---------------- kernel 0: zero the accumulator scratch ----------------
__global__ void zero_accum_kernel(){
    int i = blockIdx.x * blockDim.x + threadIdx.x;
    if (i < BH * 624) g_accum[i] = 0.0f;
}

// ---------------- kernel 1: fused gram (q . k^T) + sum-squares ----------------
// grid = (16, BH) = 512 CTAs; each CTA handles 1024 j's of one (b,head) as
// 4 chunks of 256 with a 2-stage cp.async ring (load c+1 overlaps compute c).
#define CH     256
#define GPITCH 260                     // 256+4: rows spread across banks, 16B aligned
#define GSTG   (2 * HD * GPITCH)       // one stage: q tile + k tile
#define NCHK   4
__global__ __launch_bounds__(256) void gram_kernel(const float* __restrict__ q,
                                                   const float* __restrict__ k){
    extern __shared__ float sm[];
    unsigned int sm_a = (unsigned int)__cvta_generic_to_shared(sm);

    const int tid = threadIdx.x;
    const int bh  = blockIdx.y;
    const int j0v = blockIdx.x * (NCHK * CH / 4);   // float4 base for this CTA

    const float4* qg = (const float4*)(q + (size_t)bh * HD * HW);
    const float4* kg = (const float4*)(k + (size_t)bh * HD * HW);

    // issue one chunk (24 x 256 of q and k) into stage slot s
    auto issue = [&](int ch, int s){
        const int base = j0v + ch * (CH / 4);
        unsigned int qa = sm_a + (unsigned)(s * GSTG) * 4;
        unsigned int ka = sm_a + (unsigned)(s * GSTG + HD * GPITCH) * 4;
        #pragma unroll
        for (int r = 0; r < HD * (CH / 4) / 256; r++){   // 6 iters
            int idx = tid + r * 256;
            int row = idx >> 6;          // /64
            int jv  = idx & 63;
            cp_async16(qa + (unsigned)(row * GPITCH + jv * 4) * 4, qg + row * (HW / 4) + base + jv);
            cp_async16(ka + (unsigned)(row * GPITCH + jv * 4) * 4, kg + row * (HW / 4) + base + jv);
        }
    };

    issue(0, 0);
    cp_commit();

    const int grp = tid >> 6;            // 0..3
    const int u   = tid & 63;
    const int tc  = u & 7;
    const int td  = u >> 3;
    const int c0  = tc * 3;
    const int d0  = td * 3;
    const int jb  = grp * 64;            // this group's j base within the chunk

    unsigned long long acc[3][3];
    #pragma unroll
    for (int i = 0; i < 3; i++)
        #pragma unroll
        for (int j = 0; j < 3; j++) acc[i][j] = 0ull;
    unsigned long long ssq = 0ull;
    const bool has_ssq = (u < 48);
    const int  srow    = (u < 24) ? u : (u < 48 ? (u - 24) : 0);
    const bool s_is_q  = (u < 24);

    for (int ch = 0; ch < NCHK; ch++){
        cp_wait<0>();
        __syncthreads();
        if (ch + 1 < NCHK) issue(ch + 1, (ch + 1) & 1);
        cp_commit();

        const float* qs = sm + (ch & 1) * GSTG;
        const float* ks = qs + HD * GPITCH;
        const float* sp = (s_is_q ? qs : ks) + srow * GPITCH;

        #pragma unroll 2
        for (int jv = 0; jv < CH / 16; jv++){      // 16 iters, 4 floats each
            const int off = jb + jv * 4;
            ulonglong2 qp[3], kp[3];
            #pragma unroll
            for (int i = 0; i < 3; i++) qp[i] = *(const ulonglong2*)(qs + (c0 + i) * GPITCH + off);
            #pragma unroll
            for (int i = 0; i < 3; i++) kp[i] = *(const ulonglong2*)(ks + (d0 + i) * GPITCH + off);
            #pragma unroll
            for (int i = 0; i < 3; i++)
                #pragma unroll
                for (int j = 0; j < 3; j++){
                    ffma2(acc[i][j], qp[i].x, kp[j].x);
                    ffma2(acc[i][j], qp[i].y, kp[j].y);
                }
            if (has_ssq){
                ulonglong2 s = *(const ulonglong2*)(sp + off);
                ffma2(ssq, s.x, s.x);
                ffma2(ssq, s.y, s.y);
            }
        }
        __syncthreads();
    }

    // cross-group reduction in smem, then atomics to global (once per CTA)
    float* red = sm;                      // [4][624]
    #pragma unroll
    for (int i = 0; i < 3; i++)
        #pragma unroll
        for (int j = 0; j < 3; j++)
            red[grp * 624 + (c0 + i) * HD + (d0 + j)] = hsum2(acc[i][j]);
    if (has_ssq) red[grp * 624 + 576 + u] = hsum2(ssq);
    __syncthreads();

    for (int idx = tid; idx < 624; idx += 256){
        float s = red[idx] + red[624 + idx] + red[1248 + idx] + red[1872 + idx];
        atomicAdd(&g_accum[bh * 624 + idx], s);
    }
}

// ---------------- kernel 2: norms -> softmax -> fold inv_k -> fold proj -> C_b ----------------
__global__ __launch_bounds__(256) void prep_kernel(const float* __restrict__ scale,
                                                   const float* __restrict__ proj){
    __shared__ float invq[CCH], invk[CCH], Wsm[NH * HD * HD];
    const int b   = blockIdx.x;
    const int tid = threadIdx.x;

    if (tid < CCH){
        int h = tid / HD, c = tid % HD;
        const float* acc = g_accum + (b * NH + h) * 624;
        invq[tid] = 1.0f / fmaxf(sqrtf(acc[576 + c]), 1e-12f);
        invk[tid] = 1.0f / fmaxf(sqrtf(acc[600 + c]), 1e-12f);
    }
    __syncthreads();

    if (tid < CCH){
        int h = tid / HD, c = tid % HD;
        const float* acc = g_accum + (b * NH + h) * 624;
        float iq = invq[tid];
        float sc = scale[h];
        float l[HD];
        float m = -1e30f;
        #pragma unroll
        for (int d = 0; d < HD; d++){
            l[d] = acc[c * HD + d] * iq * invk[h * HD + d] * sc;
            m = fmaxf(m, l[d]);
        }
        float s = 0.0f;
        #pragma unroll
        for (int d = 0; d < HD; d++){ l[d] = expf(l[d] - m); s += l[d]; }
        float inv = 1.0f / s;
        #pragma unroll
        for (int d = 0; d < HD; d++)
            Wsm[(h * HD + c) * HD + d] = l[d] * inv * invk[h * HD + d];
    }
    __syncthreads();

    for (int idx = tid; idx < CCH * CCH; idx += 256){
        int o  = idx / CCH;
        int g  = idx % CCH;
        int hg = g / HD, dl = g % HD;
        const float* pw = proj + o * CCH + hg * HD;
        const float* wr = Wsm + hg * HD * HD + dl;
        float s = 0.0f;
        #pragma unroll
        for (int cl = 0; cl < HD; cl++) s += pw[cl] * wr[cl * HD];
        g_C[b * CCH * CCH + idx] = s;
    }
}

// ---------------- kernel 3: out[b] = C_b (192x192) @ k[b] (192x16384) ----------------
// grid = (HW/GN, CCH/GM, B), block = 256, 2 CTAs/SM.
// A (GM x 192) full-K resident transposed; B: 3-stage cp.async ring, ONE barrier per k-tile.
// Thread micro-tile 8(o) x 8(n); n split lane*4 / lane*4+128 (conflict-free LDS.128).
#define GM  64
#define GN  256
#define GK  16
#define NKT (CCH / GK)    // 12
#define NST 3
#define APITCH 68
__global__ __launch_bounds__(256, 2) void out_gemm_kernel(const float* __restrict__ kin,
                                                          float* __restrict__ out){
    extern __shared__ float sm[];
    float* As = sm;                       // [192][APITCH] : As[g][o]
    float* Bs = sm + CCH * APITCH;        // [NST][GK][GN]
    unsigned int bs_a = (unsigned int)__cvta_generic_to_shared(Bs);

    const int tid = threadIdx.x;
    const int nt  = blockIdx.x;
    const int mt  = blockIdx.y;
    const int b   = blockIdx.z;

    const float* Bg = kin + (size_t)b * CCH * HW + (size_t)nt * GN;

    auto issueB = [&](int kt, int s){
        #pragma unroll
        for (int r = 0; r < 4; r++){
            int idx = tid + r * 256;          // 0..1023
            int g   = idx >> 6;               // 16 rows, 64 float4 each
            int nv  = idx & 63;
            cp_async16(bs_a + (unsigned)(s * GK * GN + g * GN + nv * 4) * 4,
                       Bg + (size_t)kt * GK * HW + (size_t)g * HW + nv * 4);
        }
    };

    // prologue: stages 0, 1 (one commit group each)
    issueB(0, 0); cp_commit();
    issueB(1, 1); cp_commit();

    // A: transpose-load C_b slice [GM][192] -> As[g][o]  (overlaps the prologue copies)
    const float* Ag = g_C + b * CCH * CCH + (size_t)mt * GM * CCH;
    for (int idx = tid; idx < GM * CCH; idx += 256){
        int o = idx / CCH;
        int g = idx % CCH;
        As[g * APITCH + o] = Ag[o * CCH + g];
    }

    const int n0    = (tid & 31) * 4;     // 0..124
    const int o_idx = (tid >> 5) * 8;     // 0..56

    unsigned long long acc[8][4];
    #pragma unroll
    for (int i = 0; i < 8; i++)
        #pragma unroll
        for (int p = 0; p < 4; p++) acc[i][p] = 0ull;

    for (int kt = 0; kt < NKT; kt++){
        cp_wait<NST - 2>();               // stage kt retired
        __syncthreads();                  // also frees slot (kt-1)%3 for reuse
        if (kt + 2 < NKT) issueB(kt + 2, (kt + 2) % NST);
        cp_commit();                      // always commit (possibly empty) to keep count

        const float* Arow = As + kt * GK * APITCH + o_idx;
        const float* Brow = Bs + (kt % NST) * GK * GN + n0;
        #pragma unroll 4
        for (int g = 0; g < GK; g++){
            float4 a0 = *(const float4*)(Arow + g * APITCH);
            float4 a1 = *(const float4*)(Arow + g * APITCH + 4);
            ulonglong2 bL = *(const ulonglong2*)(Brow + g * GN);
            ulonglong2 bH = *(const ulonglong2*)(Brow + g * GN + 128);
            unsigned long long d0 = dup2(a0.x), d1 = dup2(a0.y), d2 = dup2(a0.z), d3 = dup2(a0.w);
            unsigned long long d4 = dup2(a1.x), d5 = dup2(a1.y), d6 = dup2(a1.z), d7 = dup2(a1.w);
            ffma2(acc[0][0], d0, bL.x); ffma2(acc[0][1], d0, bL.y);
            ffma2(acc[0][2], d0, bH.x); ffma2(acc[0][3], d0, bH.y);
            ffma2(acc[1][0], d1, bL.x); ffma2(acc[1][1], d1, bL.y);
            ffma2(acc[1][2], d1, bH.x); ffma2(acc[1][3], d1, bH.y);
            ffma2(acc[2][0], d2, bL.x); ffma2(acc[2][1], d2, bL.y);
            ffma2(acc[2][2], d2, bH.x); ffma2(acc[2][3], d2, bH.y);
            ffma2(acc[3][0], d3, bL.x); ffma2(acc[3][1], d3, bL.y);
            ffma2(acc[3][2], d3, bH.x); ffma2(acc[3][3], d3, bH.y);
            ffma2(acc[4][0], d4, bL.x); ffma2(acc[4][1], d4, bL.y);
            ffma2(acc[4][2], d4, bH.x); ffma2(acc[4][3], d4, bH.y);
            ffma2(acc[5][0], d5, bL.x); ffma2(acc[5][1], d5, bL.y);
            ffma2(acc[5][2], d5, bH.x); ffma2(acc[5][3], d5, bH.y);
            ffma2(acc[6][0], d6, bL.x); ffma2(acc[6][1], d6, bL.y);
            ffma2(acc[6][2], d6, bH.x); ffma2(acc[6][3], d6, bH.y);
            ffma2(acc[7][0], d7, bL.x); ffma2(acc[7][1], d7, bL.y);
            ffma2(acc[7][2], d7, bH.x); ffma2(acc[7][3], d7, bH.y);
        }
    }

    float* og = out + (size_t)b * CCH * HW + (size_t)(mt * GM + o_idx) * HW + (size_t)nt * GN + n0;
    #pragma unroll
    for (int i = 0; i < 8; i++){
        float2 p0 = unpack2(acc[i][0]);
        float2 p1 = unpack2(acc[i][1]);
        float2 p2 = unpack2(acc[i][2]);
        float2 p3 = unpack2(acc[i][3]);
        *(float4*)(og + (size_t)i * HW)       = make_float4(p0.x, p0.y, p1.x, p1.y);
        *(float4*)(og + (size_t)i * HW + 128) = make_float4(p2.x, p2.y, p3.x, p3.y);
    }
}

// ---------------- launch ----------------
extern "C" void kernel_launch(void* const* d_in, const int* in_sizes, int n_in,
                              void* d_out, int out_size){
    const float *in1 = nullptr, *in2 = nullptr, *scale = nullptr, *proj = nullptr;
    for (int i = 0; i < n_in; i++){
        int s = in_sizes[i];
        if (s == BB * CCH * HW){
            if (!in1) in1 = (const float*)d_in[i];
            else if (!in2) in2 = (const float*)d_in[i];
        } else if (s == NH){
            scale = (const float*)d_in[i];
        } else if (s == CCH * CCH){
            proj = (const float*)d_in[i];
        }
    }
    float* out = (float*)d_out;

    const int smem1 = (2 * GSTG) * (int)sizeof(float);                          // ~99.8 KB
    const int smem3 = (CCH * APITCH + NST * GK * GN) * (int)sizeof(float);      // ~99 KB
    cudaFuncSetAttribute(gram_kernel,     cudaFuncAttributeMaxDynamicSharedMemorySize, smem1);
    cudaFuncSetAttribute(out_gemm_kernel, cudaFuncAttributeMaxDynamicSharedMemorySize, smem3);

    zero_accum_kernel<<<(BH * 624 + 255) / 256, 256>>>();

    dim3 g1(HW / (NCHK * CH), BH);    // (16, 32)
    gram_kernel<<<g1, 256, smem1>>>(in1, in2);

    prep_kernel<<<BB, 256>>>(scale, proj);

    dim3 g3(HW / GN, CCH / GM, BB);   // (64, 3, 4)
    out_gemm_kernel<<<g3, 256, smem3>>>(in2, out);
}

// round 16
// speedup vs baseline: 1.4969x; 1.4969x over previous
#include <cuda_runtime.h>
#include <math.h>

#define HW   16384
#define CCH  192
#define BB   4
#define NH   8
#define HD   24
#define BH   (BB*NH)      // 32

// scratch (no allocations allowed)
__device__ float g_accum[BH * 624];     // per bh: 576 gram dots + 24 ssq_q + 24 ssq_k
__device__ float g_C[BB * CCH * CCH];   // combined (proj @ blockdiag(W)) per batch

// ---------------- packed fp32x2 helpers ----------------
__device__ __forceinline__ void ffma2(unsigned long long &d, unsigned long long a, unsigned long long b){
    asm("fma.rn.f32x2 %0, %1, %2, %0;" : "+l"(d) : "l"(a), "l"(b));
}
__device__ __forceinline__ unsigned long long dup2(float a){
    unsigned long long r; asm("mov.b64 %0, {%1, %1};" : "=l"(r) : "f"(a)); return r;
}
__device__ __forceinline__ float hsum2(unsigned long long v){
    float lo, hi; asm("mov.b64 {%0, %1}, %2;" : "=f"(lo), "=f"(hi) : "l"(v)); return lo + hi;
}
__device__ __forceinline__ float2 unpack2(unsigned long long v){
    float2 r; asm("mov.b64 {%0, %1}, %2;" : "=f"(r.x), "=f"(r.y) : "l"(v)); return r;
}

// ---------------- cp.async helpers ----------------
__device__ __forceinline__ void cp_async16(unsigned int saddr, const void* gptr){
    asm volatile("cp.async.cg.shared.global [%0], [%1], 16;" :: "r"(saddr), "l"(gptr) : "memory");
}
__device__ __forceinline__ void cp_commit(){ asm volatile("cp.async.commit_group;" ::: "memory"); }
template<int N>
__device__ __forceinline__ void cp_wait(){ asm volatile("cp.async.wait_group %0;" :: "n"(N) : "memory"); }

// ---------------- kernel 0: zero the accumulator scratch ----------------
__global__ void zero_accum_kernel(){
    int i = blockIdx.x * blockDim.x + threadIdx.x;
    if (i < BH * 624) g_accum[i] = 0.0f;
}

// ---------------- kernel 1: fused gram (q . k^T) + sum-squares ----------------
// grid = (16, BH) = 512 CTAs; each CTA handles 1024 j's of one (b,head) as
// 4 chunks of 256 with a 2-stage cp.async ring (load c+1 overlaps compute c).
#define CH     256
#define GPITCH 260                     // 256+4: rows spread across banks, 16B aligned
#define GSTG   (2 * HD * GPITCH)       // one stage: q tile + k tile
#define NCHK   4
__global__ __launch_bounds__(256) void gram_kernel(const float* __restrict__ q,
                                                   const float* __restrict__ k){
    extern __shared__ float sm[];
    unsigned int sm_a = (unsigned int)__cvta_generic_to_shared(sm);

    const int tid = threadIdx.x;
    const int bh  = blockIdx.y;
    const int j0v = blockIdx.x * (NCHK * CH / 4);   // float4 base for this CTA

    const float4* qg = (const float4*)(q + (size_t)bh * HD * HW);
    const float4* kg = (const float4*)(k + (size_t)bh * HD * HW);

    // issue one chunk (24 x 256 of q and k) into stage slot s
    auto issue = [&](int ch, int s){
        const int base = j0v + ch * (CH / 4);
        unsigned int qa = sm_a + (unsigned)(s * GSTG) * 4;
        unsigned int ka = sm_a + (unsigned)(s * GSTG + HD * GPITCH) * 4;
        #pragma unroll
        for (int r = 0; r < HD * (CH / 4) / 256; r++){   // 6 iters
            int idx = tid + r * 256;
            int row = idx >> 6;          // /64
            int jv  = idx & 63;
            cp_async16(qa + (unsigned)(row * GPITCH + jv * 4) * 4, qg + row * (HW / 4) + base + jv);
            cp_async16(ka + (unsigned)(row * GPITCH + jv * 4) * 4, kg + row * (HW / 4) + base + jv);
        }
    };

    issue(0, 0);
    cp_commit();

    const int grp = tid >> 6;            // 0..3
    const int u   = tid & 63;
    const int tc  = u & 7;
    const int td  = u >> 3;
    const int c0  = tc * 3;
    const int d0  = td * 3;
    const int jb  = grp * 64;            // this group's j base within the chunk

    unsigned long long acc[3][3];
    #pragma unroll
    for (int i = 0; i < 3; i++)
        #pragma unroll
        for (int j = 0; j < 3; j++) acc[i][j] = 0ull;
    unsigned long long ssq = 0ull;
    const bool has_ssq = (u < 48);
    const int  srow    = (u < 24) ? u : (u < 48 ? (u - 24) : 0);
    const bool s_is_q  = (u < 24);

    for (int ch = 0; ch < NCHK; ch++){
        cp_wait<0>();
        __syncthreads();
        if (ch + 1 < NCHK) issue(ch + 1, (ch + 1) & 1);
        cp_commit();

        const float* qs = sm + (ch & 1) * GSTG;
        const float* ks = qs + HD * GPITCH;
        const float* sp = (s_is_q ? qs : ks) + srow * GPITCH;

        #pragma unroll 2
        for (int jv = 0; jv < CH / 16; jv++){      // 16 iters, 4 floats each
            const int off = jb + jv * 4;
            ulonglong2 qp[3], kp[3];
            #pragma unroll
            for (int i = 0; i < 3; i++) qp[i] = *(const ulonglong2*)(qs + (c0 + i) * GPITCH + off);
            #pragma unroll
            for (int i = 0; i < 3; i++) kp[i] = *(const ulonglong2*)(ks + (d0 + i) * GPITCH + off);
            #pragma unroll
            for (int i = 0; i < 3; i++)
                #pragma unroll
                for (int j = 0; j < 3; j++){
                    ffma2(acc[i][j], qp[i].x, kp[j].x);
                    ffma2(acc[i][j], qp[i].y, kp[j].y);
                }
            if (has_ssq){
                ulonglong2 s = *(const ulonglong2*)(sp + off);
                ffma2(ssq, s.x, s.x);
                ffma2(ssq, s.y, s.y);
            }
        }
        __syncthreads();
    }

    // cross-group reduction in smem, then atomics to global (once per CTA)
    float* red = sm;                      // [4][624]
    #pragma unroll
    for (int i = 0; i < 3; i++)
        #pragma unroll
        for (int j = 0; j < 3; j++)
            red[grp * 624 + (c0 + i) * HD + (d0 + j)] = hsum2(acc[i][j]);
    if (has_ssq) red[grp * 624 + 576 + u] = hsum2(ssq);
    __syncthreads();

    for (int idx = tid; idx < 624; idx += 256){
        float s = red[idx] + red[624 + idx] + red[1248 + idx] + red[1872 + idx];
        atomicAdd(&g_accum[bh * 624 + idx], s);
    }
}

// ---------------- kernel 2: norms -> softmax -> fold inv_k -> fold proj -> C_b ----------------
__global__ __launch_bounds__(256) void prep_kernel(const float* __restrict__ scale,
                                                   const float* __restrict__ proj){
    __shared__ float invq[CCH], invk[CCH], Wsm[NH * HD * HD];
    const int b   = blockIdx.x;
    const int tid = threadIdx.x;

    if (tid < CCH){
        int h = tid / HD, c = tid % HD;
        const float* acc = g_accum + (b * NH + h) * 624;
        invq[tid] = 1.0f / fmaxf(sqrtf(acc[576 + c]), 1e-12f);
        invk[tid] = 1.0f / fmaxf(sqrtf(acc[600 + c]), 1e-12f);
    }
    __syncthreads();

    if (tid < CCH){
        int h = tid / HD, c = tid % HD;
        const float* acc = g_accum + (b * NH + h) * 624;
        float iq = invq[tid];
        float sc = scale[h];
        float l[HD];
        float m = -1e30f;
        #pragma unroll
        for (int d = 0; d < HD; d++){
            l[d] = acc[c * HD + d] * iq * invk[h * HD + d] * sc;
            m = fmaxf(m, l[d]);
        }
        float s = 0.0f;
        #pragma unroll
        for (int d = 0; d < HD; d++){ l[d] = expf(l[d] - m); s += l[d]; }
        float inv = 1.0f / s;
        #pragma unroll
        for (int d = 0; d < HD; d++)
            Wsm[(h * HD + c) * HD + d] = l[d] * inv * invk[h * HD + d];
    }
    __syncthreads();

    for (int idx = tid; idx < CCH * CCH; idx += 256){
        int o  = idx / CCH;
        int g  = idx % CCH;
        int hg = g / HD, dl = g % HD;
        const float* pw = proj + o * CCH + hg * HD;
        const float* wr = Wsm + hg * HD * HD + dl;
        float s = 0.0f;
        #pragma unroll
        for (int cl = 0; cl < HD; cl++) s += pw[cl] * wr[cl * HD];
        g_C[b * CCH * CCH + idx] = s;
    }
}

// ---------------- kernel 3: out[b] = C_b (192x192) @ k[b] (192x16384) ----------------
// grid = (HW/GN, CCH/GM, B), block = 256, 2 CTAs/SM.
// A (GM x 192) full-K resident transposed; B: 3-stage cp.async ring, ONE barrier per k-tile.
// Thread micro-tile 8(o) x 8(n); n split lane*4 / lane*4+128 (conflict-free LDS.128).
#define GM  64
#define GN  256
#define GK  16
#define NKT (CCH / GK)    // 12
#define NST 3
#define APITCH 68
__global__ __launch_bounds__(256, 2) void out_gemm_kernel(const float* __restrict__ kin,
                                                          float* __restrict__ out){
    extern __shared__ float sm[];
    float* As = sm;                       // [192][APITCH] : As[g][o]
    float* Bs = sm + CCH * APITCH;        // [NST][GK][GN]
    unsigned int bs_a = (unsigned int)__cvta_generic_to_shared(Bs);

    const int tid = threadIdx.x;
    const int nt  = blockIdx.x;
    const int mt  = blockIdx.y;
    const int b   = blockIdx.z;

    const float* Bg = kin + (size_t)b * CCH * HW + (size_t)nt * GN;

    auto issueB = [&](int kt, int s){
        #pragma unroll
        for (int r = 0; r < 4; r++){
            int idx = tid + r * 256;          // 0..1023
            int g   = idx >> 6;               // 16 rows, 64 float4 each
            int nv  = idx & 63;
            cp_async16(bs_a + (unsigned)(s * GK * GN + g * GN + nv * 4) * 4,
                       Bg + (size_t)kt * GK * HW + (size_t)g * HW + nv * 4);
        }
    };

    // prologue: stages 0, 1 (one commit group each)
    issueB(0, 0); cp_commit();
    issueB(1, 1); cp_commit();

    // A: transpose-load C_b slice [GM][192] -> As[g][o]  (overlaps the prologue copies)
    const float* Ag = g_C + b * CCH * CCH + (size_t)mt * GM * CCH;
    for (int idx = tid; idx < GM * CCH; idx += 256){
        int o = idx / CCH;
        int g = idx % CCH;
        As[g * APITCH + o] = Ag[o * CCH + g];
    }

    const int n0    = (tid & 31) * 4;     // 0..124
    const int o_idx = (tid >> 5) * 8;     // 0..56

    unsigned long long acc[8][4];
    #pragma unroll
    for (int i = 0; i < 8; i++)
        #pragma unroll
        for (int p = 0; p < 4; p++) acc[i][p] = 0ull;

    for (int kt = 0; kt < NKT; kt++){
        cp_wait<NST - 2>();               // stage kt retired
        __syncthreads();                  // also frees slot (kt-1)%3 for reuse
        if (kt + 2 < NKT) issueB(kt + 2, (kt + 2) % NST);
        cp_commit();                      // always commit (possibly empty) to keep count

        const float* Arow = As + kt * GK * APITCH + o_idx;
        const float* Brow = Bs + (kt % NST) * GK * GN + n0;
        #pragma unroll 4
        for (int g = 0; g < GK; g++){
            float4 a0 = *(const float4*)(Arow + g * APITCH);
            float4 a1 = *(const float4*)(Arow + g * APITCH + 4);
            ulonglong2 bL = *(const ulonglong2*)(Brow + g * GN);
            ulonglong2 bH = *(const ulonglong2*)(Brow + g * GN + 128);
            unsigned long long d0 = dup2(a0.x), d1 = dup2(a0.y), d2 = dup2(a0.z), d3 = dup2(a0.w);
            unsigned long long d4 = dup2(a1.x), d5 = dup2(a1.y), d6 = dup2(a1.z), d7 = dup2(a1.w);
            ffma2(acc[0][0], d0, bL.x); ffma2(acc[0][1], d0, bL.y);
            ffma2(acc[0][2], d0, bH.x); ffma2(acc[0][3], d0, bH.y);
            ffma2(acc[1][0], d1, bL.x); ffma2(acc[1][1], d1, bL.y);
            ffma2(acc[1][2], d1, bH.x); ffma2(acc[1][3], d1, bH.y);
            ffma2(acc[2][0], d2, bL.x); ffma2(acc[2][1], d2, bL.y);
            ffma2(acc[2][2], d2, bH.x); ffma2(acc[2][3], d2, bH.y);
            ffma2(acc[3][0], d3, bL.x); ffma2(acc[3][1], d3, bL.y);
            ffma2(acc[3][2], d3, bH.x); ffma2(acc[3][3], d3, bH.y);
            ffma2(acc[4][0], d4, bL.x); ffma2(acc[4][1], d4, bL.y);
            ffma2(acc[4][2], d4, bH.x); ffma2(acc[4][3], d4, bH.y);
            ffma2(acc[5][0], d5, bL.x); ffma2(acc[5][1], d5, bL.y);
            ffma2(acc[5][2], d5, bH.x); ffma2(acc[5][3], d5, bH.y);
            ffma2(acc[6][0], d6, bL.x); ffma2(acc[6][1], d6, bL.y);
            ffma2(acc[6][2], d6, bH.x); ffma2(acc[6][3], d6, bH.y);
            ffma2(acc[7][0], d7, bL.x); ffma2(acc[7][1], d7, bL.y);
            ffma2(acc[7][2], d7, bH.x); ffma2(acc[7][3], d7, bH.y);
        }
    }

    float* og = out + (size_t)b * CCH * HW + (size_t)(mt * GM + o_idx) * HW + (size_t)nt * GN + n0;
    #pragma unroll
    for (int i = 0; i < 8; i++){
        float2 p0 = unpack2(acc[i][0]);
        float2 p1 = unpack2(acc[i][1]);
        float2 p2 = unpack2(acc[i][2]);
        float2 p3 = unpack2(acc[i][3]);
        *(float4*)(og + (size_t)i * HW)       = make_float4(p0.x, p0.y, p1.x, p1.y);
        *(float4*)(og + (size_t)i * HW + 128) = make_float4(p2.x, p2.y, p3.x, p3.y);
    }
}

// ---------------- launch ----------------
extern "C" void kernel_launch(void* const* d_in, const int* in_sizes, int n_in,
                              void* d_out, int out_size){
    const float *in1 = nullptr, *in2 = nullptr, *scale = nullptr, *proj = nullptr;
    for (int i = 0; i < n_in; i++){
        int s = in_sizes[i];
        if (s == BB * CCH * HW){
            if (!in1) in1 = (const float*)d_in[i];
            else if (!in2) in2 = (const float*)d_in[i];
        } else if (s == NH){
            scale = (const float*)d_in[i];
        } else if (s == CCH * CCH){
            proj = (const float*)d_in[i];
        }
    }
    float* out = (float*)d_out;

    const int smem1 = (2 * GSTG) * (int)sizeof(float);                          // ~99.8 KB
    const int smem3 = (CCH * APITCH + NST * GK * GN) * (int)sizeof(float);      // ~99 KB
    cudaFuncSetAttribute(gram_kernel,     cudaFuncAttributeMaxDynamicSharedMemorySize, smem1);
    cudaFuncSetAttribute(out_gemm_kernel, cudaFuncAttributeMaxDynamicSharedMemorySize, smem3);

    zero_accum_kernel<<<(BH * 624 + 255) / 256, 256>>>();

    dim3 g1(HW / (NCHK * CH), BH);    // (16, 32)
    gram_kernel<<<g1, 256, smem1>>>(in1, in2);

    prep_kernel<<<BB, 256>>>(scale, proj);

    dim3 g3(HW / GN, CCH / GM, BB);   // (64, 3, 4)
    out_gemm_kernel<<<g3, 256, smem3>>>(in2, out);
}

// round 17
// speedup vs baseline: 1.9376x; 1.2945x over previous
#include <cuda_runtime.h>
#include <math.h>

#define HW   16384
#define CCH  192
#define BB   4
#define NH   8
#define HD   24
#define BH   (BB*NH)      // 32
#define NJT  16           // gram j-tiles

// scratch (no allocations allowed)
__device__ float g_part[NJT * BH * 624];  // per (jtile,bh): 576 gram dots + 24 ssq_q + 24 ssq_k
__device__ float g_W[BB * NH * HD * HD];  // softmax*invk weights per batch
__device__ float g_C[BB * CCH * CCH];     // combined (proj @ blockdiag(W)) per batch

// ---------------- packed fp32x2 helpers ----------------
__device__ __forceinline__ void ffma2(unsigned long long &d, unsigned long long a, unsigned long long b){
    asm("fma.rn.f32x2 %0, %1, %2, %0;" : "+l"(d) : "l"(a), "l"(b));
}
__device__ __forceinline__ unsigned long long dup2(float a){
    unsigned long long r; asm("mov.b64 %0, {%1, %1};" : "=l"(r) : "f"(a)); return r;
}
__device__ __forceinline__ float hsum2(unsigned long long v){
    float lo, hi; asm("mov.b64 {%0, %1}, %2;" : "=f"(lo), "=f"(hi) : "l"(v)); return lo + hi;
}
__device__ __forceinline__ float2 unpack2(unsigned long long v){
    float2 r; asm("mov.b64 {%0, %1}, %2;" : "=f"(r.x), "=f"(r.y) : "l"(v)); return r;
}

// ---------------- cp.async helpers ----------------
__device__ __forceinline__ void cp_async16(unsigned int saddr, const void* gptr){
    asm volatile("cp.async.cg.shared.global [%0], [%1], 16;" :: "r"(saddr), "l"(gptr) : "memory");
}
__device__ __forceinline__ void cp_commit(){ asm volatile("cp.async.commit_group;" ::: "memory"); }
template<int N>
__device__ __forceinline__ void cp_wait(){ asm volatile("cp.async.wait_group %0;" :: "n"(N) : "memory"); }

// ---------------- kernel 1: fused gram (q . k^T) + sum-squares ----------------
// grid = (NJT, BH) = 512 CTAs x 512 threads; each CTA handles 1024 j's as
// 4 chunks of 256 with a 2-stage cp.async ring. 8 groups of 64 threads,
// each group owns 32 j's; thread owns a 3x3 (c,d) microtile.
#define CH     256
#define GPITCH 260                     // 256+4: 16B-aligned rows, bank-spread
#define GSTG   (2 * HD * GPITCH)       // one stage: q tile + k tile
#define NCHK   4
__global__ __launch_bounds__(512) void gram_kernel(const float* __restrict__ q,
                                                   const float* __restrict__ k){
    extern __shared__ float sm[];
    unsigned int sm_a = (unsigned int)__cvta_generic_to_shared(sm);

    const int tid = threadIdx.x;
    const int bh  = blockIdx.y;
    const int j0v = blockIdx.x * (NCHK * CH / 4);   // float4 base for this CTA

    const float4* qg = (const float4*)(q + (size_t)bh * HD * HW);
    const float4* kg = (const float4*)(k + (size_t)bh * HD * HW);

    auto issue = [&](int ch, int s){
        const int base = j0v + ch * (CH / 4);
        unsigned int qa = sm_a + (unsigned)(s * GSTG) * 4;
        unsigned int ka = sm_a + (unsigned)(s * GSTG + HD * GPITCH) * 4;
        #pragma unroll
        for (int r = 0; r < HD * (CH / 4) / 512; r++){   // 3 iters
            int idx = tid + r * 512;
            int row = idx >> 6;          // /64
            int jv  = idx & 63;
            cp_async16(qa + (unsigned)(row * GPITCH + jv * 4) * 4, qg + row * (HW / 4) + base + jv);
            cp_async16(ka + (unsigned)(row * GPITCH + jv * 4) * 4, kg + row * (HW / 4) + base + jv);
        }
    };

    issue(0, 0);
    cp_commit();

    const int grp = tid >> 6;            // 0..7
    const int u   = tid & 63;
    const int c0  = (u & 7) * 3;
    const int d0  = (u >> 3) * 3;
    const int jb  = grp * 32;            // group's j base within the chunk

    unsigned long long acc[3][3];
    #pragma unroll
    for (int i = 0; i < 3; i++)
        #pragma unroll
        for (int j = 0; j < 3; j++) acc[i][j] = 0ull;
    unsigned long long ssq = 0ull;
    const bool has_ssq = (u < 48);
    const int  srow    = (u < 24) ? u : (u < 48 ? (u - 24) : 0);
    const bool s_is_q  = (u < 24);

    for (int ch = 0; ch < NCHK; ch++){
        cp_wait<0>();
        __syncthreads();
        if (ch + 1 < NCHK) issue(ch + 1, (ch + 1) & 1);
        cp_commit();

        const float* qs = sm + (ch & 1) * GSTG;
        const float* ks = qs + HD * GPITCH;
        const float* sp = (s_is_q ? qs : ks) + srow * GPITCH;

        #pragma unroll
        for (int jv = 0; jv < 8; jv++){              // 8 iters x 4 floats = 32 j
            const int off = jb + jv * 4;
            ulonglong2 qp[3], kp[3];
            #pragma unroll
            for (int i = 0; i < 3; i++) qp[i] = *(const ulonglong2*)(qs + (c0 + i) * GPITCH + off);
            #pragma unroll
            for (int i = 0; i < 3; i++) kp[i] = *(const ulonglong2*)(ks + (d0 + i) * GPITCH + off);
            #pragma unroll
            for (int i = 0; i < 3; i++)
                #pragma unroll
                for (int j = 0; j < 3; j++){
                    ffma2(acc[i][j], qp[i].x, kp[j].x);
                    ffma2(acc[i][j], qp[i].y, kp[j].y);
                }
            if (has_ssq){
                ulonglong2 s = *(const ulonglong2*)(sp + off);
                ffma2(ssq, s.x, s.x);
                ffma2(ssq, s.y, s.y);
            }
        }
        __syncthreads();
    }

    // cross-group reduction in smem, then per-CTA partial to global (no atomics)
    float* red = sm;                      // [8][624] = 19.9 KB, aliases stage 0
    #pragma unroll
    for (int i = 0; i < 3; i++)
        #pragma unroll
        for (int j = 0; j < 3; j++)
            red[grp * 624 + (c0 + i) * HD + (d0 + j)] = hsum2(acc[i][j]);
    if (has_ssq) red[grp * 624 + 576 + u] = hsum2(ssq);
    __syncthreads();

    float* dst = g_part + ((size_t)blockIdx.x * BH + bh) * 624;
    for (int idx = tid; idx < 624; idx += 512){
        float s = 0.f;
        #pragma unroll
        for (int g = 0; g < 8; g++) s += red[g * 624 + idx];
        dst[idx] = s;
    }
}

// ---------------- kernel 2a: reduce partials -> norms -> softmax -> W ----------------
// grid = BB, block = 256
__global__ __launch_bounds__(256) void prep_kernel(const float* __restrict__ scale){
    __shared__ float accs[NH * 624];     // 4992 floats
    __shared__ float invk[CCH];
    __shared__ float Wsm[NH * HD * HD];
    const int b   = blockIdx.x;
    const int tid = threadIdx.x;

    // reduce NJT partials for this batch's 8 heads
    for (int idx = tid; idx < NH * 624; idx += 256){
        int h = idx / 624, e = idx % 624;
        float s = 0.f;
        #pragma unroll
        for (int jt = 0; jt < NJT; jt++)
            s += g_part[((size_t)jt * BH + b * NH + h) * 624 + e];
        accs[idx] = s;
    }
    __syncthreads();

    if (tid < CCH){
        int h = tid / HD, c = tid % HD;
        invk[tid] = 1.0f / fmaxf(sqrtf(accs[h * 624 + 600 + c]), 1e-12f);
    }
    __syncthreads();

    if (tid < CCH){
        int h = tid / HD, c = tid % HD;
        const float* acc = accs + h * 624;
        float iq = 1.0f / fmaxf(sqrtf(acc[576 + c]), 1e-12f);
        float sc = scale[h];
        float l[HD];
        float m = -1e30f;
        #pragma unroll
        for (int d = 0; d < HD; d++){
            l[d] = acc[c * HD + d] * iq * invk[h * HD + d] * sc;
            m = fmaxf(m, l[d]);
        }
        float s = 0.0f;
        #pragma unroll
        for (int d = 0; d < HD; d++){ l[d] = expf(l[d] - m); s += l[d]; }
        float inv = 1.0f / s;
        #pragma unroll
        for (int d = 0; d < HD; d++)
            Wsm[(h * HD + c) * HD + d] = l[d] * inv * invk[h * HD + d];
    }
    __syncthreads();

    for (int idx = tid; idx < NH * HD * HD; idx += 256)
        g_W[b * NH * HD * HD + idx] = Wsm[idx];
}

// ---------------- kernel 2b: C_b[o][g] = sum_cl proj[o][hg*24+cl] * W[hg][cl][dl] ----------------
// grid = (6, BB): each block does 32 rows of C_b. block = 256.
__global__ __launch_bounds__(256) void prep2_kernel(const float* __restrict__ proj){
    __shared__ float Wsm[NH * HD * HD];
    const int b   = blockIdx.y;
    const int o0  = blockIdx.x * 32;
    const int tid = threadIdx.x;

    for (int idx = tid; idx < NH * HD * HD; idx += 256)
        Wsm[idx] = g_W[b * NH * HD * HD + idx];
    __syncthreads();

    for (int idx = tid; idx < 32 * CCH; idx += 256){
        int ol = idx / CCH;
        int g  = idx % CCH;
        int hg = g / HD, dl = g % HD;
        const float* pw = proj + (size_t)(o0 + ol) * CCH + hg * HD;
        const float* wr = Wsm + hg * HD * HD + dl;
        float s = 0.0f;
        #pragma unroll
        for (int cl = 0; cl < HD; cl++) s += pw[cl] * wr[cl * HD];
        g_C[b * CCH * CCH + (size_t)(o0 + ol) * CCH + g] = s;
    }
}

// ---------------- kernel 3: out[b] = C_b (192x192) @ k[b] (192x16384) ----------------
#define GM  64
#define GN  256
#define GK  16
#define NKT (CCH / GK)    // 12
#define NST 3
#define APITCH 68
__global__ __launch_bounds__(256, 2) void out_gemm_kernel(const float* __restrict__ kin,
                                                          float* __restrict__ out){
    extern __shared__ float sm[];
    float* As = sm;                       // [192][APITCH] : As[g][o]
    float* Bs = sm + CCH * APITCH;        // [NST][GK][GN]
    unsigned int bs_a = (unsigned int)__cvta_generic_to_shared(Bs);

    const int tid = threadIdx.x;
    const int nt  = blockIdx.x;
    const int mt  = blockIdx.y;
    const int b   = blockIdx.z;

    const float* Bg = kin + (size_t)b * CCH * HW + (size_t)nt * GN;

    auto issueB = [&](int kt, int s){
        #pragma unroll
        for (int r = 0; r < 4; r++){
            int idx = tid + r * 256;          // 0..1023
            int g   = idx >> 6;               // 16 rows, 64 float4 each
            int nv  = idx & 63;
            cp_async16(bs_a + (unsigned)(s * GK * GN + g * GN + nv * 4) * 4,
                       Bg + (size_t)kt * GK * HW + (size_t)g * HW + nv * 4);
        }
    };

    issueB(0, 0); cp_commit();
    issueB(1, 1); cp_commit();

    const float* Ag = g_C + b * CCH * CCH + (size_t)mt * GM * CCH;
    for (int idx = tid; idx < GM * CCH; idx += 256){
        int o = idx / CCH;
        int g = idx % CCH;
        As[g * APITCH + o] = Ag[o * CCH + g];
    }

    const int n0    = (tid & 31) * 4;
    const int o_idx = (tid >> 5) * 8;

    unsigned long long acc[8][4];
    #pragma unroll
    for (int i = 0; i < 8; i++)
        #pragma unroll
        for (int p = 0; p < 4; p++) acc[i][p] = 0ull;

    for (int kt = 0; kt < NKT; kt++){
        cp_wait<NST - 2>();
        __syncthreads();
        if (kt + 2 < NKT) issueB(kt + 2, (kt + 2) % NST);
        cp_commit();

        const float* Arow = As + kt * GK * APITCH + o_idx;
        const float* Brow = Bs + (kt % NST) * GK * GN + n0;
        #pragma unroll 4
        for (int g = 0; g < GK; g++){
            float4 a0 = *(const float4*)(Arow + g * APITCH);
            float4 a1 = *(const float4*)(Arow + g * APITCH + 4);
            ulonglong2 bL = *(const ulonglong2*)(Brow + g * GN);
            ulonglong2 bH = *(const ulonglong2*)(Brow + g * GN + 128);
            unsigned long long d0 = dup2(a0.x), d1 = dup2(a0.y), d2 = dup2(a0.z), d3 = dup2(a0.w);
            unsigned long long d4 = dup2(a1.x), d5 = dup2(a1.y), d6 = dup2(a1.z), d7 = dup2(a1.w);
            ffma2(acc[0][0], d0, bL.x); ffma2(acc[0][1], d0, bL.y);
            ffma2(acc[0][2], d0, bH.x); ffma2(acc[0][3], d0, bH.y);
            ffma2(acc[1][0], d1, bL.x); ffma2(acc[1][1], d1, bL.y);
            ffma2(acc[1][2], d1, bH.x); ffma2(acc[1][3], d1, bH.y);
            ffma2(acc[2][0], d2, bL.x); ffma2(acc[2][1], d2, bL.y);
            ffma2(acc[2][2], d2, bH.x); ffma2(acc[2][3], d2, bH.y);
            ffma2(acc[3][0], d3, bL.x); ffma2(acc[3][1], d3, bL.y);
            ffma2(acc[3][2], d3, bH.x); ffma2(acc[3][3], d3, bH.y);
            ffma2(acc[4][0], d4, bL.x); ffma2(acc[4][1], d4, bL.y);
            ffma2(acc[4][2], d4, bH.x); ffma2(acc[4][3], d4, bH.y);
            ffma2(acc[5][0], d5, bL.x); ffma2(acc[5][1], d5, bL.y);
            ffma2(acc[5][2], d5, bH.x); ffma2(acc[5][3], d5, bH.y);
            ffma2(acc[6][0], d6, bL.x); ffma2(acc[6][1], d6, bL.y);
            ffma2(acc[6][2], d6, bH.x); ffma2(acc[6][3], d6, bH.y);
            ffma2(acc[7][0], d7, bL.x); ffma2(acc[7][1], d7, bL.y);
            ffma2(acc[7][2], d7, bH.x); ffma2(acc[7][3], d7, bH.y);
        }
    }

    float* og = out + (size_t)b * CCH * HW + (size_t)(mt * GM + o_idx) * HW + (size_t)nt * GN + n0;
    #pragma unroll
    for (int i = 0; i < 8; i++){
        float2 p0 = unpack2(acc[i][0]);
        float2 p1 = unpack2(acc[i][1]);
        float2 p2 = unpack2(acc[i][2]);
        float2 p3 = unpack2(acc[i][3]);
        *(float4*)(og + (size_t)i * HW)       = make_float4(p0.x, p0.y, p1.x, p1.y);
        *(float4*)(og + (size_t)i * HW + 128) = make_float4(p2.x, p2.y, p3.x, p3.y);
    }
}

// ---------------- launch ----------------
extern "C" void kernel_launch(void* const* d_in, const int* in_sizes, int n_in,
                              void* d_out, int out_size){
    const float *in1 = nullptr, *in2 = nullptr, *scale = nullptr, *proj = nullptr;
    for (int i = 0; i < n_in; i++){
        int s = in_sizes[i];
        if (s == BB * CCH * HW){
            if (!in1) in1 = (const float*)d_in[i];
            else if (!in2) in2 = (const float*)d_in[i];
        } else if (s == NH){
            scale = (const float*)d_in[i];
        } else if (s == CCH * CCH){
            proj = (const float*)d_in[i];
        }
    }
    float* out = (float*)d_out;

    const int smem1 = (2 * GSTG) * (int)sizeof(float);                          // ~99.8 KB
    const int smem3 = (CCH * APITCH + NST * GK * GN) * (int)sizeof(float);      // ~99 KB
    cudaFuncSetAttribute(gram_kernel,     cudaFuncAttributeMaxDynamicSharedMemorySize, smem1);
    cudaFuncSetAttribute(out_gemm_kernel, cudaFuncAttributeMaxDynamicSharedMemorySize, smem3);

    dim3 g1(NJT, BH);                 // (16, 32)
    gram_kernel<<<g1, 512, smem1>>>(in1, in2);

    prep_kernel<<<BB, 256>>>(scale);

    dim3 g2b(6, BB);
    prep2_kernel<<<g2b, 256>>>(proj);

    dim3 g3(HW / GN, CCH / GM, BB);   // (64, 3, 4)
    out_gemm_kernel<<<g3, 256, smem3>>>(in2, out);
}